// round 5
// baseline (speedup 1.0000x reference)
#include <cuda_runtime.h>
#include <math.h>
#include <stdint.h>

// Problem constants
#define BB 4
#define SS 1024
#define DD 1024
#define HH 16
#define HD 64
#define NEG_V 10000.0f

// Scratch (static device arrays; no allocation allowed)
__device__ float g_qkv[BB * SS * 3 * DD];     // [4096, 3072]
__device__ float g_am[BB * SS * DD];          // merged heads [4096, 1024]

// ---------------------------------------------------------------------------
// tf32 helpers
// ---------------------------------------------------------------------------
__device__ __forceinline__ uint32_t f2tf(float f) {
    uint32_t u;
    asm("cvt.rna.tf32.f32 %0, %1;" : "=r"(u) : "f"(f));
    return u;
}

__device__ __forceinline__ void mma8(float* c, const uint32_t* a, const uint32_t* b) {
    asm volatile(
        "mma.sync.aligned.m16n8k8.row.col.f32.tf32.tf32.f32 "
        "{%0,%1,%2,%3}, {%4,%5,%6,%7}, {%8,%9}, {%0,%1,%2,%3};\n"
        : "+f"(c[0]), "+f"(c[1]), "+f"(c[2]), "+f"(c[3])
        : "r"(a[0]), "r"(a[1]), "r"(a[2]), "r"(a[3]), "r"(b[0]), "r"(b[1]));
}

// Fragment-pack index helpers (m16n8k8):
//  A value (r in 0..15 within m16 tile, kk in 0..7 within k8):
//    lane = ((r&7)<<2) | (kk&3),  reg = (r>>3) | ((kk>>2)<<1)   -> 4 regs, LDS.128
//  B value (n col c in 0..7, kk in 0..7):
//    lane = (c<<2) | (kk&3),      reg = kk>>2                   -> 2 regs, LDS.64

// ---------------------------------------------------------------------------
// Generic tf32 GEMM: C[M,N] = A[M,K] @ B[K,N] + bias[N]
// BM=128, BN=128, BK=16, 256 threads (8 warps: 4 in M x 2 in N, warp 32x64)
// Double-buffered smem, ONE __syncthreads per K-chunk.
// ---------------------------------------------------------------------------
__global__ __launch_bounds__(256) void gemm_tf32_bias(
    const float* __restrict__ A, const float* __restrict__ B,
    const float* __restrict__ bias, float* __restrict__ C,
    int K, int lda, int ldb, int ldc)
{
    __shared__ __align__(16) uint32_t Ap[2][2][8][32][4];   // [buf][ksub][mi][lane][reg]
    __shared__ __align__(16) uint32_t Bp[2][2][16][32][2];  // [buf][ksub][ni][lane][reg]

    const int tid = threadIdx.x;
    const int lane = tid & 31;
    const int warp = tid >> 5;
    const int wm = warp & 3, wn = warp >> 2;
    const int rowStart = blockIdx.y * 128;
    const int colStart = blockIdx.x * 128;

    float acc[2][8][4];
#pragma unroll
    for (int mi = 0; mi < 2; mi++)
#pragma unroll
        for (int ni = 0; ni < 8; ni++)
#pragma unroll
            for (int r = 0; r < 4; r++) acc[mi][ni][r] = 0.f;

    float4 aR[2], bR[2];

#define G_LOADG(kb) do {                                                          \
    _Pragma("unroll")                                                             \
    for (int i = 0; i < 2; i++) {                                                 \
        int lin = tid * 2 + i;                                                    \
        aR[i] = *reinterpret_cast<const float4*>(                                 \
            &A[(size_t)(rowStart + (lin >> 2)) * lda + (kb) + ((lin & 3) << 2)]); \
        bR[i] = *reinterpret_cast<const float4*>(                                 \
            &B[(size_t)((kb) + (lin >> 5)) * ldb + colStart + ((lin & 31) << 2)]);\
    } } while (0)

#define G_STORES(bf) do {                                                         \
    _Pragma("unroll")                                                             \
    for (int i = 0; i < 2; i++) {                                                 \
        int lin = tid * 2 + i;                                                    \
        int m = lin >> 2; int k0l = (lin & 3) << 2; int mi = m >> 4; int r = m & 15; \
        float va[4] = {aR[i].x, aR[i].y, aR[i].z, aR[i].w};                       \
        _Pragma("unroll")                                                         \
        for (int j = 0; j < 4; j++) {                                             \
            int k = k0l + j; int kk = k & 7; int ks = k >> 3;                     \
            Ap[bf][ks][mi][((r & 7) << 2) | (kk & 3)][(r >> 3) | ((kk >> 2) << 1)] = f2tf(va[j]); \
        }                                                                         \
        int kB = lin >> 5; int n0 = (lin & 31) << 2; int kkB = kB & 7; int ksB = kB >> 3; \
        float vb[4] = {bR[i].x, bR[i].y, bR[i].z, bR[i].w};                       \
        _Pragma("unroll")                                                         \
        for (int j = 0; j < 4; j++) {                                             \
            int n = n0 + j;                                                       \
            Bp[bf][ksB][n >> 3][((n & 7) << 2) | (kkB & 3)][kkB >> 2] = f2tf(vb[j]); \
        }                                                                         \
    } } while (0)

#define G_COMPUTE(bf) do {                                                        \
    _Pragma("unroll")                                                             \
    for (int ks = 0; ks < 2; ks++) {                                              \
        uint32_t af[2][4]; uint32_t bfr[8][2];                                    \
        _Pragma("unroll")                                                         \
        for (int mi = 0; mi < 2; mi++)                                            \
            *reinterpret_cast<uint4*>(af[mi]) =                                   \
                *reinterpret_cast<const uint4*>(Ap[bf][ks][wm * 2 + mi][lane]);   \
        _Pragma("unroll")                                                         \
        for (int ni = 0; ni < 8; ni++)                                            \
            *reinterpret_cast<uint2*>(bfr[ni]) =                                  \
                *reinterpret_cast<const uint2*>(Bp[bf][ks][wn * 8 + ni][lane]);   \
        _Pragma("unroll")                                                         \
        for (int mi = 0; mi < 2; mi++)                                            \
            _Pragma("unroll")                                                     \
            for (int ni = 0; ni < 8; ni++)                                        \
                mma8(acc[mi][ni], af[mi], bfr[ni]);                               \
    } } while (0)

    G_LOADG(0);
    G_STORES(0);
    __syncthreads();
    int p = 0;
    for (int kb = 16; kb < K; kb += 16) {
        G_LOADG(kb);
        G_COMPUTE(p);
        G_STORES(p ^ 1);
        __syncthreads();
        p ^= 1;
    }
    G_COMPUTE(p);

    // epilogue
#pragma unroll
    for (int mi = 0; mi < 2; mi++)
#pragma unroll
        for (int ni = 0; ni < 8; ni++) {
            int row = rowStart + wm * 32 + mi * 16 + (lane >> 2);
            int col = colStart + wn * 64 + ni * 8 + (lane & 3) * 2;
            float b0 = bias[col], b1 = bias[col + 1];
            C[(size_t)row * ldc + col]           = acc[mi][ni][0] + b0;
            C[(size_t)row * ldc + col + 1]       = acc[mi][ni][1] + b1;
            C[(size_t)(row + 8) * ldc + col]     = acc[mi][ni][2] + b0;
            C[(size_t)(row + 8) * ldc + col + 1] = acc[mi][ni][3] + b1;
        }
}

// ---------------------------------------------------------------------------
// QK^T (tf32 mma) with scale + causal mask + additive mask epilogue.
// Per z = b*H+h: scores[1024,1024]. 128x128 tile, K-dim = 64 (4 chunks of 16).
// Double-buffered, one sync per chunk.
// ---------------------------------------------------------------------------
__global__ __launch_bounds__(256) void qk_tf32(
    const float* __restrict__ qkv, const float* __restrict__ mask,
    float* __restrict__ Wout)
{
    __shared__ __align__(16) uint32_t Ap[2][2][8][32][4];
    __shared__ __align__(16) uint32_t Bp[2][2][16][32][2];

    const int tid = threadIdx.x;
    const int lane = tid & 31;
    const int warp = tid >> 5;
    const int wm = warp & 3, wn = warp >> 2;
    const int rowStart = blockIdx.y * 128;
    const int colStart = blockIdx.x * 128;
    const int z = blockIdx.z;
    const int b = z / HH;
    const int h = z % HH;

    const float* Qb = qkv + (size_t)b * SS * 3 * DD + h * HD;
    const float* Kb = Qb + DD;

    float acc[2][8][4];
#pragma unroll
    for (int mi = 0; mi < 2; mi++)
#pragma unroll
        for (int ni = 0; ni < 8; ni++)
#pragma unroll
            for (int r = 0; r < 4; r++) acc[mi][ni][r] = 0.f;

    float4 aR[2], bR[2];

#define QK_LOADG(kb) do {                                                         \
    _Pragma("unroll")                                                             \
    for (int i = 0; i < 2; i++) {                                                 \
        int lin = tid * 2 + i;                                                    \
        aR[i] = *reinterpret_cast<const float4*>(                                 \
            &Qb[(size_t)(rowStart + (lin >> 2)) * (3 * DD) + (kb) + ((lin & 3) << 2)]); \
        bR[i] = *reinterpret_cast<const float4*>(                                 \
            &Kb[(size_t)(colStart + (lin >> 2)) * (3 * DD) + (kb) + ((lin & 3) << 2)]); \
    } } while (0)

#define QK_STORES(bf) do {                                                        \
    _Pragma("unroll")                                                             \
    for (int i = 0; i < 2; i++) {                                                 \
        int lin = tid * 2 + i;                                                    \
        int m = lin >> 2; int k0l = (lin & 3) << 2; int mi = m >> 4; int r = m & 15; \
        float va[4] = {aR[i].x, aR[i].y, aR[i].z, aR[i].w};                       \
        float vb[4] = {bR[i].x, bR[i].y, bR[i].z, bR[i].w};                       \
        _Pragma("unroll")                                                         \
        for (int j = 0; j < 4; j++) {                                             \
            int k = k0l + j; int kk = k & 7; int ks = k >> 3;                     \
            Ap[bf][ks][mi][((r & 7) << 2) | (kk & 3)][(r >> 3) | ((kk >> 2) << 1)] = f2tf(va[j]); \
            /* B: n = m (this lin indexes K-matrix row = output col) */           \
            Bp[bf][ks][m >> 3][((m & 7) << 2) | (kk & 3)][kk >> 2] = f2tf(vb[j]); \
        }                                                                         \
    } } while (0)

    QK_LOADG(0);
    QK_STORES(0);
    __syncthreads();
    int p = 0;
    for (int kb = 16; kb < HD; kb += 16) {
        QK_LOADG(kb);
        G_COMPUTE(p);
        QK_STORES(p ^ 1);
        __syncthreads();
        p ^= 1;
    }
    G_COMPUTE(p);

    const float* mrow = mask + (size_t)b * SS;
#pragma unroll
    for (int mi = 0; mi < 2; mi++)
#pragma unroll
        for (int ni = 0; ni < 8; ni++) {
            int row0 = rowStart + wm * 32 + mi * 16 + (lane >> 2);
            int col = colStart + wn * 64 + ni * 8 + (lane & 3) * 2;
            float m0 = mrow[col], m1 = mrow[col + 1];
#pragma unroll
            for (int half = 0; half < 2; half++) {
                int row = row0 + half * 8;
                float v0 = (row >= col)     ? acc[mi][ni][half * 2 + 0] * 0.125f : -NEG_V;
                float v1 = (row >= col + 1) ? acc[mi][ni][half * 2 + 1] * 0.125f : -NEG_V;
                float* crow = &Wout[((size_t)z * SS + row) * SS + col];
                crow[0] = v0 + m0;
                crow[1] = v1 + m1;
            }
        }
}

// ---------------------------------------------------------------------------
// Row softmax in place over W: 65536 rows of 1024. One block (256 thr) per row.
// ---------------------------------------------------------------------------
__global__ __launch_bounds__(256) void softmax_rows(float* __restrict__ W)
{
    __shared__ float red[8];
    const int tid = threadIdx.x;
    float* row = W + (size_t)blockIdx.x * SS;

    float4 v = *reinterpret_cast<const float4*>(&row[tid * 4]);
    float m = fmaxf(fmaxf(v.x, v.y), fmaxf(v.z, v.w));
#pragma unroll
    for (int o = 16; o > 0; o >>= 1) m = fmaxf(m, __shfl_xor_sync(0xffffffffu, m, o));
    if ((tid & 31) == 0) red[tid >> 5] = m;
    __syncthreads();
    if (tid < 32) {
        float t = (tid < 8) ? red[tid] : -INFINITY;
#pragma unroll
        for (int o = 4; o > 0; o >>= 1) t = fmaxf(t, __shfl_xor_sync(0xffffffffu, t, o));
        if (tid == 0) red[0] = t;
    }
    __syncthreads();
    m = red[0];

    float4 e;
    e.x = __expf(v.x - m);
    e.y = __expf(v.y - m);
    e.z = __expf(v.z - m);
    e.w = __expf(v.w - m);
    float s = e.x + e.y + e.z + e.w;
#pragma unroll
    for (int o = 16; o > 0; o >>= 1) s += __shfl_xor_sync(0xffffffffu, s, o);
    __syncthreads();
    if ((tid & 31) == 0) red[tid >> 5] = s;
    __syncthreads();
    if (tid < 32) {
        float t = (tid < 8) ? red[tid] : 0.f;
#pragma unroll
        for (int o = 4; o > 0; o >>= 1) t += __shfl_xor_sync(0xffffffffu, t, o);
        if (tid == 0) red[0] = t;
    }
    __syncthreads();
    float inv = 1.0f / red[0];

    e.x *= inv; e.y *= inv; e.z *= inv; e.w *= inv;
    *reinterpret_cast<float4*>(&row[tid * 4]) = e;
}

// ---------------------------------------------------------------------------
// AV (tf32 mma): per z = b*H+h: C[1024,64] = W_z[1024,1024] @ V_z[1024,64].
// BM=128, BN=64, BK=16, 256 threads (8 warps, each 16 rows x 64 cols).
// Double-buffered, one sync per chunk. Writes merged-head layout into g_am.
// ---------------------------------------------------------------------------
__global__ __launch_bounds__(256) void av_tf32(
    const float* __restrict__ W, const float* __restrict__ qkv,
    float* __restrict__ Am)
{
    __shared__ __align__(16) uint32_t Ap[2][2][8][32][4];
    __shared__ __align__(16) uint32_t Bp[2][2][8][32][2];

    const int tid = threadIdx.x;
    const int lane = tid & 31;
    const int warp = tid >> 5;
    const int rowStart = blockIdx.x * 128;
    const int z = blockIdx.y;
    const int b = z / HH;
    const int h = z % HH;

    const float* Wb = W + (size_t)z * SS * SS;
    const float* Vb = qkv + (size_t)b * SS * 3 * DD + 2 * DD + h * HD;

    float acc[8][4];
#pragma unroll
    for (int ni = 0; ni < 8; ni++)
#pragma unroll
        for (int r = 0; r < 4; r++) acc[ni][r] = 0.f;

    float4 aR[2], bR;

#define AV_LOADG(kb) do {                                                         \
    _Pragma("unroll")                                                             \
    for (int i = 0; i < 2; i++) {                                                 \
        int lin = tid * 2 + i;                                                    \
        aR[i] = *reinterpret_cast<const float4*>(                                 \
            &Wb[(size_t)(rowStart + (lin >> 2)) * SS + (kb) + ((lin & 3) << 2)]); \
    }                                                                             \
    bR = *reinterpret_cast<const float4*>(                                        \
        &Vb[(size_t)((kb) + (tid >> 4)) * (3 * DD) + ((tid & 15) << 2)]);         \
    } while (0)

#define AV_STORES(bf) do {                                                        \
    _Pragma("unroll")                                                             \
    for (int i = 0; i < 2; i++) {                                                 \
        int lin = tid * 2 + i;                                                    \
        int m = lin >> 2; int k0l = (lin & 3) << 2; int mi = m >> 4; int r = m & 15; \
        float va[4] = {aR[i].x, aR[i].y, aR[i].z, aR[i].w};                       \
        _Pragma("unroll")                                                         \
        for (int j = 0; j < 4; j++) {                                             \
            int k = k0l + j; int kk = k & 7; int ks = k >> 3;                     \
            Ap[bf][ks][mi][((r & 7) << 2) | (kk & 3)][(r >> 3) | ((kk >> 2) << 1)] = f2tf(va[j]); \
        }                                                                         \
    }                                                                             \
    {                                                                             \
        int kB = tid >> 4; int n0 = (tid & 15) << 2;                              \
        int kkB = kB & 7; int ksB = kB >> 3;                                      \
        float vb[4] = {bR.x, bR.y, bR.z, bR.w};                                   \
        _Pragma("unroll")                                                         \
        for (int j = 0; j < 4; j++) {                                             \
            int n = n0 + j;                                                       \
            Bp[bf][ksB][n >> 3][((n & 7) << 2) | (kkB & 3)][kkB >> 2] = f2tf(vb[j]); \
        }                                                                         \
    } } while (0)

#define AV_COMPUTE(bf) do {                                                       \
    _Pragma("unroll")                                                             \
    for (int ks = 0; ks < 2; ks++) {                                              \
        uint32_t af[4]; uint32_t bfr[8][2];                                       \
        *reinterpret_cast<uint4*>(af) =                                           \
            *reinterpret_cast<const uint4*>(Ap[bf][ks][warp][lane]);              \
        _Pragma("unroll")                                                         \
        for (int ni = 0; ni < 8; ni++)                                            \
            *reinterpret_cast<uint2*>(bfr[ni]) =                                  \
                *reinterpret_cast<const uint2*>(Bp[bf][ks][ni][lane]);            \
        _Pragma("unroll")                                                         \
        for (int ni = 0; ni < 8; ni++)                                            \
            mma8(acc[ni], af, bfr[ni]);                                           \
    } } while (0)

    AV_LOADG(0);
    AV_STORES(0);
    __syncthreads();
    int p = 0;
    for (int kb = 16; kb < SS; kb += 16) {
        AV_LOADG(kb);
        AV_COMPUTE(p);
        AV_STORES(p ^ 1);
        __syncthreads();
        p ^= 1;
    }
    AV_COMPUTE(p);

#pragma unroll
    for (int ni = 0; ni < 8; ni++) {
        int row = rowStart + warp * 16 + (lane >> 2);
        int col = h * HD + ni * 8 + (lane & 3) * 2;
        float* o0 = &Am[((size_t)b * SS + row) * DD + col];
        float* o1 = &Am[((size_t)b * SS + row + 8) * DD + col];
        o0[0] = acc[ni][0]; o0[1] = acc[ni][1];
        o1[0] = acc[ni][2]; o1[1] = acc[ni][3];
    }
}

// ---------------------------------------------------------------------------
extern "C" void kernel_launch(void* const* d_in, const int* in_sizes, int n_in,
                              void* d_out, int out_size)
{
    const float* x      = (const float*)d_in[0];   // [4,1024,1024]
    const float* mask   = (const float*)d_in[1];   // [4,1,1,1024]
    const float* w_attn = (const float*)d_in[2];   // [1024,3072]
    const float* b_attn = (const float*)d_in[3];   // [1,3072]
    const float* w_proj = (const float*)d_in[4];   // [1024,1024]
    const float* b_proj = (const float*)d_in[5];   // [1,1024]

    float* out = (float*)d_out;
    float* a_out = out;                                  // [4,1024,1024]
    float* w_out = out + (size_t)BB * SS * DD;           // [4,16,1024,1024]

    float* qkv = nullptr;
    float* am = nullptr;
    cudaGetSymbolAddress((void**)&qkv, g_qkv);
    cudaGetSymbolAddress((void**)&am, g_am);

    // 1) qkv = x @ w_attn + b_attn   (4096 x 3072 x 1024)
    {
        dim3 grid(3 * DD / 128, BB * SS / 128);
        gemm_tf32_bias<<<grid, 256>>>(x, w_attn, b_attn, qkv,
                                      DD, DD, 3 * DD, 3 * DD);
    }
    // 2) scores = scale * Q@K^T with causal mask (+mask) -> w_out
    {
        dim3 grid(SS / 128, SS / 128, BB * HH);
        qk_tf32<<<grid, 256>>>(qkv, mask, w_out);
    }
    // 3) softmax rows in place
    {
        softmax_rows<<<BB * HH * SS, 256>>>(w_out);
    }
    // 4) a_heads = W @ V, merged into g_am
    {
        dim3 grid(SS / 128, BB * HH);
        av_tf32<<<grid, 256>>>(w_out, qkv, am);
    }
    // 5) a = a_merged @ w_proj + b_proj -> a_out
    {
        dim3 grid(DD / 128, BB * SS / 128);
        gemm_tf32_bias<<<grid, 256>>>(am, w_proj, b_proj, a_out,
                                      DD, DD, DD, DD);
    }
}

// round 6
// speedup vs baseline: 2.9814x; 2.9814x over previous
#include <cuda_runtime.h>
#include <math.h>
#include <stdint.h>

// Problem constants
#define BB 4
#define SS 1024
#define DD 1024
#define HH 16
#define HD 64
#define NEG_V 10000.0f

// Scratch (static device arrays; no allocation allowed)
__device__ float g_qkv[BB * SS * 3 * DD];   // [4096,3072] tf32-rounded
__device__ float g_am[BB * SS * DD];        // [4096,1024] tf32-rounded
__device__ float g_xtf[BB * SS * DD];       // x converted to tf32 bits
__device__ float g_watf[DD * 3 * DD];       // w_attn converted
__device__ float g_wptf[DD * DD];           // w_proj converted

// ---------------------------------------------------------------------------
// helpers
// ---------------------------------------------------------------------------
__device__ __forceinline__ uint32_t f2tf(float f) {
    uint32_t u;
    asm("cvt.rna.tf32.f32 %0, %1;" : "=r"(u) : "f"(f));
    return u;
}

__device__ __forceinline__ void mma8(float* c, const uint32_t* a, const uint32_t* b) {
    asm volatile(
        "mma.sync.aligned.m16n8k8.row.col.f32.tf32.tf32.f32 "
        "{%0,%1,%2,%3}, {%4,%5,%6,%7}, {%8,%9}, {%0,%1,%2,%3};\n"
        : "+f"(c[0]), "+f"(c[1]), "+f"(c[2]), "+f"(c[3])
        : "r"(a[0]), "r"(a[1]), "r"(a[2]), "r"(a[3]), "r"(b[0]), "r"(b[1]));
}

__device__ __forceinline__ void cp16(uint32_t dst, const void* src) {
    asm volatile("cp.async.cg.shared.global [%0], [%1], 16;\n" :: "r"(dst), "l"(src));
}
#define CP_COMMIT() asm volatile("cp.async.commit_group;\n" ::: "memory")
#define CP_WAIT(N)  asm volatile("cp.async.wait_group %0;\n" :: "n"(N) : "memory")

// m16n8k8 fragment maps (row.col):
//  A(16x8):  a0=A[g][t] a1=A[g+8][t] a2=A[g][t+4] a3=A[g+8][t+4]  (g=lane>>2,t=lane&3)
//  B(8x8):   b0=B[t][g] b1=B[t+4][g]
//  C(16x8):  c0=C[g][2t] c1=C[g][2t+1] c2=C[g+8][2t] c3=C[g+8][2t+1]

// ---------------------------------------------------------------------------
// Elementwise tf32 pre-convert (n multiple of 1024)
// ---------------------------------------------------------------------------
__global__ __launch_bounds__(256) void cvt_tf32(
    const float* __restrict__ src, float* __restrict__ dst)
{
    int i = (blockIdx.x * 256 + threadIdx.x) * 4;
    float4 v = *reinterpret_cast<const float4*>(src + i);
    uint4 o;
    o.x = f2tf(v.x); o.y = f2tf(v.y); o.z = f2tf(v.z); o.w = f2tf(v.w);
    *reinterpret_cast<uint4*>(dst + i) = o;
}

// ---------------------------------------------------------------------------
// Generic tf32 GEMM on pre-converted inputs: C[M,N] = A@B + bias
// BM=128 BN=128 BK=16, 256 thr (8 warps, warp 32x64), 3-stage cp.async ring.
// smem: As[3][128][20] + Bs[3][16][136] (uint32) = 56832 B
// A-gather stride 20 (20r%32=4r) and B-gather stride 136 (136k%32=8k):
// perfectly bank-partitioned scalar LDS.
// ---------------------------------------------------------------------------
#define GA_ST 20
#define GB_ST 136
#define GA_SZ (128 * GA_ST)   // 2560
#define GB_SZ (16 * GB_ST)    // 2176
#define G_SMEM ((3 * (GA_SZ + GB_SZ)) * 4)

template<bool ROUND>
__global__ __launch_bounds__(256, 2) void gemm_tc(
    const float* __restrict__ A, const float* __restrict__ B,
    const float* __restrict__ bias, float* __restrict__ C,
    int K, int lda, int ldb, int ldc)
{
    extern __shared__ __align__(16) uint32_t sm[];
    uint32_t* As = sm;
    uint32_t* Bs = sm + 3 * GA_SZ;
    const uint32_t smb = (uint32_t)__cvta_generic_to_shared(sm);

    const int tid = threadIdx.x, lane = tid & 31, warp = tid >> 5;
    const int wm = warp & 3, wn = warp >> 2;
    const int rowStart = blockIdx.y * 128, colStart = blockIdx.x * 128;

    float acc[2][8][4];
#pragma unroll
    for (int mi = 0; mi < 2; mi++)
#pragma unroll
        for (int ni = 0; ni < 8; ni++)
#pragma unroll
            for (int r = 0; r < 4; r++) acc[mi][ni][r] = 0.f;

#define G_LOAD(kb, s) do {                                                       \
    _Pragma("unroll")                                                            \
    for (int i = 0; i < 2; i++) {                                                \
        int v = tid * 2 + i;                                                     \
        int r = v >> 2, c4 = (v & 3) << 2;                                       \
        cp16(smb + ((s) * GA_SZ + r * GA_ST + c4) * 4,                           \
             &A[(size_t)(rowStart + r) * lda + (kb) + c4]);                      \
    }                                                                            \
    _Pragma("unroll")                                                            \
    for (int i = 0; i < 2; i++) {                                                \
        int v = tid * 2 + i;                                                     \
        int r = v >> 5, c4 = (v & 31) << 2;                                      \
        cp16(smb + (3 * GA_SZ + (s) * GB_SZ + r * GB_ST + c4) * 4,               \
             &B[(size_t)((kb) + r) * ldb + colStart + c4]);                      \
    } } while (0)

#define G_COMP(s) do {                                                           \
    const uint32_t* Av = As + (s) * GA_SZ;                                       \
    const uint32_t* Bv = Bs + (s) * GB_SZ;                                       \
    _Pragma("unroll")                                                            \
    for (int ks = 0; ks < 2; ks++) {                                             \
        uint32_t af[2][4];                                                       \
        _Pragma("unroll")                                                        \
        for (int mi = 0; mi < 2; mi++) {                                         \
            int r = wm * 32 + mi * 16 + (lane >> 2);                             \
            int c = ks * 8 + (lane & 3);                                         \
            af[mi][0] = Av[r * GA_ST + c];                                       \
            af[mi][1] = Av[(r + 8) * GA_ST + c];                                 \
            af[mi][2] = Av[r * GA_ST + c + 4];                                   \
            af[mi][3] = Av[(r + 8) * GA_ST + c + 4];                             \
        }                                                                        \
        _Pragma("unroll")                                                        \
        for (int ni = 0; ni < 8; ni++) {                                         \
            int n = wn * 64 + ni * 8 + (lane >> 2);                              \
            uint32_t bf[2];                                                      \
            bf[0] = Bv[(ks * 8 + (lane & 3)) * GB_ST + n];                       \
            bf[1] = Bv[(ks * 8 + 4 + (lane & 3)) * GB_ST + n];                   \
            mma8(acc[0][ni], af[0], bf);                                         \
            mma8(acc[1][ni], af[1], bf);                                         \
        }                                                                        \
    } } while (0)

    const int NC = K / 16;
    G_LOAD(0, 0); CP_COMMIT();
    G_LOAD(16, 1); CP_COMMIT();
    int st = 0;
    for (int c = 0; c < NC; c++) {
        CP_WAIT(1);
        __syncthreads();
        G_COMP(st);
        int s2 = st + 2; if (s2 >= 3) s2 -= 3;
        if (c + 2 < NC) G_LOAD((c + 2) * 16, s2);
        CP_COMMIT();
        st++; if (st >= 3) st = 0;
    }

#pragma unroll
    for (int mi = 0; mi < 2; mi++)
#pragma unroll
        for (int ni = 0; ni < 8; ni++) {
            int row = rowStart + wm * 32 + mi * 16 + (lane >> 2);
            int col = colStart + wn * 64 + ni * 8 + (lane & 3) * 2;
            float b0 = bias[col], b1 = bias[col + 1];
            float v00 = acc[mi][ni][0] + b0, v01 = acc[mi][ni][1] + b1;
            float v10 = acc[mi][ni][2] + b0, v11 = acc[mi][ni][3] + b1;
            if (ROUND) {
                C[(size_t)row * ldc + col]           = __uint_as_float(f2tf(v00));
                C[(size_t)row * ldc + col + 1]       = __uint_as_float(f2tf(v01));
                C[(size_t)(row + 8) * ldc + col]     = __uint_as_float(f2tf(v10));
                C[(size_t)(row + 8) * ldc + col + 1] = __uint_as_float(f2tf(v11));
            } else {
                C[(size_t)row * ldc + col]           = v00;
                C[(size_t)row * ldc + col + 1]       = v01;
                C[(size_t)(row + 8) * ldc + col]     = v10;
                C[(size_t)(row + 8) * ldc + col + 1] = v11;
            }
        }
}

// ---------------------------------------------------------------------------
// QK^T: per z, 128x128 tile, K=64 single-shot (Q,K pre-rounded in g_qkv).
// smem: Qs[128][68] + Ks[128][68] = 69632 B. Stride 68: 68r%32=4r -> clean.
// ---------------------------------------------------------------------------
#define QK_ST 68
#define QK_SZ (128 * QK_ST)
#define QK_SMEM (2 * QK_SZ * 4)

__global__ __launch_bounds__(256, 2) void qk_tc(
    const float* __restrict__ qkv, const float* __restrict__ mask,
    float* __restrict__ Wout)
{
    extern __shared__ __align__(16) uint32_t sm[];
    uint32_t* Qs = sm;
    uint32_t* Ks = sm + QK_SZ;
    const uint32_t smb = (uint32_t)__cvta_generic_to_shared(sm);

    const int tid = threadIdx.x, lane = tid & 31, warp = tid >> 5;
    const int wm = warp & 3, wn = warp >> 2;
    const int rowStart = blockIdx.y * 128, colStart = blockIdx.x * 128;
    const int z = blockIdx.z, b = z >> 4, h = z & 15;

    const float* Qb = qkv + (size_t)b * SS * 3 * DD + h * HD;
    const float* Kb = Qb + DD;

#pragma unroll
    for (int i = 0; i < 8; i++) {
        int v = tid + i * 256;
        int r = v >> 4, c4 = (v & 15) << 2;
        cp16(smb + (r * QK_ST + c4) * 4,
             &Qb[(size_t)(rowStart + r) * (3 * DD) + c4]);
        cp16(smb + (QK_SZ + r * QK_ST + c4) * 4,
             &Kb[(size_t)(colStart + r) * (3 * DD) + c4]);
    }
    CP_COMMIT();

    float acc[2][8][4];
#pragma unroll
    for (int mi = 0; mi < 2; mi++)
#pragma unroll
        for (int ni = 0; ni < 8; ni++)
#pragma unroll
            for (int r = 0; r < 4; r++) acc[mi][ni][r] = 0.f;

    CP_WAIT(0);
    __syncthreads();

#pragma unroll
    for (int ks = 0; ks < 8; ks++) {
        uint32_t af[2][4];
#pragma unroll
        for (int mi = 0; mi < 2; mi++) {
            int r = wm * 32 + mi * 16 + (lane >> 2);
            int c = ks * 8 + (lane & 3);
            af[mi][0] = Qs[r * QK_ST + c];
            af[mi][1] = Qs[(r + 8) * QK_ST + c];
            af[mi][2] = Qs[r * QK_ST + c + 4];
            af[mi][3] = Qs[(r + 8) * QK_ST + c + 4];
        }
#pragma unroll
        for (int ni = 0; ni < 8; ni++) {
            int n = wn * 64 + ni * 8 + (lane >> 2);
            uint32_t bf[2];
            bf[0] = Ks[n * QK_ST + ks * 8 + (lane & 3)];
            bf[1] = Ks[n * QK_ST + ks * 8 + 4 + (lane & 3)];
            mma8(acc[0][ni], af[0], bf);
            mma8(acc[1][ni], af[1], bf);
        }
    }

    const float* mrow = mask + (size_t)b * SS;
#pragma unroll
    for (int mi = 0; mi < 2; mi++)
#pragma unroll
        for (int ni = 0; ni < 8; ni++) {
            int row0 = rowStart + wm * 32 + mi * 16 + (lane >> 2);
            int col = colStart + wn * 64 + ni * 8 + (lane & 3) * 2;
            float m0 = mrow[col], m1 = mrow[col + 1];
#pragma unroll
            for (int half = 0; half < 2; half++) {
                int row = row0 + half * 8;
                float v0 = (row >= col)     ? acc[mi][ni][half * 2 + 0] * 0.125f : -NEG_V;
                float v1 = (row >= col + 1) ? acc[mi][ni][half * 2 + 1] * 0.125f : -NEG_V;
                float* crow = &Wout[((size_t)z * SS + row) * SS + col];
                crow[0] = v0 + m0;
                crow[1] = v1 + m1;
            }
        }
}

// ---------------------------------------------------------------------------
// Row softmax in place: 65536 rows of 1024, one 256-thr block per row.
// ---------------------------------------------------------------------------
__global__ __launch_bounds__(256) void softmax_rows(float* __restrict__ W)
{
    __shared__ float red[8];
    const int tid = threadIdx.x;
    float* row = W + (size_t)blockIdx.x * SS;

    float4 v = *reinterpret_cast<const float4*>(&row[tid * 4]);
    float m = fmaxf(fmaxf(v.x, v.y), fmaxf(v.z, v.w));
#pragma unroll
    for (int o = 16; o > 0; o >>= 1) m = fmaxf(m, __shfl_xor_sync(0xffffffffu, m, o));
    if ((tid & 31) == 0) red[tid >> 5] = m;
    __syncthreads();
    if (tid < 32) {
        float t = (tid < 8) ? red[tid] : -INFINITY;
#pragma unroll
        for (int o = 4; o > 0; o >>= 1) t = fmaxf(t, __shfl_xor_sync(0xffffffffu, t, o));
        if (tid == 0) red[0] = t;
    }
    __syncthreads();
    m = red[0];

    float4 e;
    e.x = __expf(v.x - m);
    e.y = __expf(v.y - m);
    e.z = __expf(v.z - m);
    e.w = __expf(v.w - m);
    float s = e.x + e.y + e.z + e.w;
#pragma unroll
    for (int o = 16; o > 0; o >>= 1) s += __shfl_xor_sync(0xffffffffu, s, o);
    __syncthreads();
    if ((tid & 31) == 0) red[tid >> 5] = s;
    __syncthreads();
    if (tid < 32) {
        float t = (tid < 8) ? red[tid] : 0.f;
#pragma unroll
        for (int o = 4; o > 0; o >>= 1) t += __shfl_xor_sync(0xffffffffu, t, o);
        if (tid == 0) red[0] = t;
    }
    __syncthreads();
    float inv = 1.0f / red[0];

    e.x *= inv; e.y *= inv; e.z *= inv; e.w *= inv;
    *reinterpret_cast<float4*>(&row[tid * 4]) = e;
}

// ---------------------------------------------------------------------------
// AV: per z, C[1024,64] = W@V. BM=128 BN=64 BK=32, 8 warps (warp 16x64),
// 3-stage cp.async ring. A (probs) converted in-loop; V pre-rounded.
// smem: As[3][128][36] + Bs[3][32][72] = 82944 B.
// ---------------------------------------------------------------------------
#define VA_ST 36
#define VB_ST 72
#define VA_SZ (128 * VA_ST)   // 4608
#define VB_SZ (32 * VB_ST)    // 2304
#define V_SMEM ((3 * (VA_SZ + VB_SZ)) * 4)

__global__ __launch_bounds__(256, 2) void av_tc(
    const float* __restrict__ W, const float* __restrict__ qkv,
    float* __restrict__ Am)
{
    extern __shared__ __align__(16) uint32_t sm[];
    uint32_t* As = sm;
    uint32_t* Bs = sm + 3 * VA_SZ;
    const uint32_t smb = (uint32_t)__cvta_generic_to_shared(sm);

    const int tid = threadIdx.x, lane = tid & 31, warp = tid >> 5;
    const int rowStart = blockIdx.x * 128;
    const int z = blockIdx.y, b = z >> 4, h = z & 15;

    const float* Wb = W + (size_t)z * SS * SS;
    const float* Vb = qkv + (size_t)b * SS * 3 * DD + 2 * DD + h * HD;

    float acc[8][4];
#pragma unroll
    for (int ni = 0; ni < 8; ni++)
#pragma unroll
        for (int r = 0; r < 4; r++) acc[ni][r] = 0.f;

#define V_LOAD(kb, s) do {                                                       \
    _Pragma("unroll")                                                            \
    for (int i = 0; i < 4; i++) {                                                \
        int v = tid + i * 256;                                                   \
        int r = v >> 3, c4 = (v & 7) << 2;                                       \
        cp16(smb + ((s) * VA_SZ + r * VA_ST + c4) * 4,                           \
             &Wb[(size_t)(rowStart + r) * SS + (kb) + c4]);                      \
    }                                                                            \
    _Pragma("unroll")                                                            \
    for (int i = 0; i < 2; i++) {                                                \
        int v = tid * 2 + i;                                                     \
        int r = v >> 4, c4 = (v & 15) << 2;                                      \
        cp16(smb + (3 * VA_SZ + (s) * VB_SZ + r * VB_ST + c4) * 4,               \
             &Vb[(size_t)((kb) + r) * (3 * DD) + c4]);                           \
    } } while (0)

#define V_COMP(s) do {                                                           \
    const uint32_t* Av = As + (s) * VA_SZ;                                       \
    const uint32_t* Bv = Bs + (s) * VB_SZ;                                       \
    _Pragma("unroll")                                                            \
    for (int ks = 0; ks < 4; ks++) {                                             \
        int r = warp * 16 + (lane >> 2);                                         \
        int c = ks * 8 + (lane & 3);                                             \
        uint32_t af[4];                                                          \
        af[0] = f2tf(__uint_as_float(Av[r * VA_ST + c]));                        \
        af[1] = f2tf(__uint_as_float(Av[(r + 8) * VA_ST + c]));                  \
        af[2] = f2tf(__uint_as_float(Av[r * VA_ST + c + 4]));                    \
        af[3] = f2tf(__uint_as_float(Av[(r + 8) * VA_ST + c + 4]));              \
        _Pragma("unroll")                                                        \
        for (int ni = 0; ni < 8; ni++) {                                         \
            int n = ni * 8 + (lane >> 2);                                        \
            uint32_t bf[2];                                                      \
            bf[0] = Bv[(ks * 8 + (lane & 3)) * VB_ST + n];                       \
            bf[1] = Bv[(ks * 8 + 4 + (lane & 3)) * VB_ST + n];                   \
            mma8(acc[ni], af, bf);                                               \
        }                                                                        \
    } } while (0)

    const int NC = SS / 32;   // 32 chunks
    V_LOAD(0, 0); CP_COMMIT();
    V_LOAD(32, 1); CP_COMMIT();
    int st = 0;
    for (int c = 0; c < NC; c++) {
        CP_WAIT(1);
        __syncthreads();
        V_COMP(st);
        int s2 = st + 2; if (s2 >= 3) s2 -= 3;
        if (c + 2 < NC) V_LOAD((c + 2) * 32, s2);
        CP_COMMIT();
        st++; if (st >= 3) st = 0;
    }

#pragma unroll
    for (int ni = 0; ni < 8; ni++) {
        int row = rowStart + warp * 16 + (lane >> 2);
        int col = h * HD + ni * 8 + (lane & 3) * 2;
        float* o0 = &Am[((size_t)b * SS + row) * DD + col];
        float* o1 = &Am[((size_t)b * SS + row + 8) * DD + col];
        o0[0] = __uint_as_float(f2tf(acc[ni][0]));
        o0[1] = __uint_as_float(f2tf(acc[ni][1]));
        o1[0] = __uint_as_float(f2tf(acc[ni][2]));
        o1[1] = __uint_as_float(f2tf(acc[ni][3]));
    }
}

// ---------------------------------------------------------------------------
extern "C" void kernel_launch(void* const* d_in, const int* in_sizes, int n_in,
                              void* d_out, int out_size)
{
    const float* x      = (const float*)d_in[0];   // [4,1024,1024]
    const float* mask   = (const float*)d_in[1];   // [4,1,1,1024]
    const float* w_attn = (const float*)d_in[2];   // [1024,3072]
    const float* b_attn = (const float*)d_in[3];   // [1,3072]
    const float* w_proj = (const float*)d_in[4];   // [1024,1024]
    const float* b_proj = (const float*)d_in[5];   // [1,1024]

    float* out = (float*)d_out;
    float* a_out = out;                                  // [4,1024,1024]
    float* w_out = out + (size_t)BB * SS * DD;           // [4,16,1024,1024]

    float *qkv, *am, *xtf, *watf, *wptf;
    cudaGetSymbolAddress((void**)&qkv, g_qkv);
    cudaGetSymbolAddress((void**)&am, g_am);
    cudaGetSymbolAddress((void**)&xtf, g_xtf);
    cudaGetSymbolAddress((void**)&watf, g_watf);
    cudaGetSymbolAddress((void**)&wptf, g_wptf);

    cudaFuncSetAttribute(gemm_tc<true>,
                         cudaFuncAttributeMaxDynamicSharedMemorySize, G_SMEM);
    cudaFuncSetAttribute(gemm_tc<false>,
                         cudaFuncAttributeMaxDynamicSharedMemorySize, G_SMEM);
    cudaFuncSetAttribute(qk_tc,
                         cudaFuncAttributeMaxDynamicSharedMemorySize, QK_SMEM);
    cudaFuncSetAttribute(av_tc,
                         cudaFuncAttributeMaxDynamicSharedMemorySize, V_SMEM);

    // 0) pre-convert inputs to tf32 bit patterns
    cvt_tf32<<<(BB * SS * DD) / 1024, 256>>>(x, xtf);
    cvt_tf32<<<(DD * 3 * DD) / 1024, 256>>>(w_attn, watf);
    cvt_tf32<<<(DD * DD) / 1024, 256>>>(w_proj, wptf);

    // 1) qkv = x @ w_attn + b_attn (rounded to tf32 on write)
    {
        dim3 grid(3 * DD / 128, BB * SS / 128);
        gemm_tc<true><<<grid, 256, G_SMEM>>>(xtf, watf, b_attn, qkv,
                                             DD, DD, 3 * DD, 3 * DD);
    }
    // 2) scores = scale * Q@K^T + causal/mask -> w_out
    {
        dim3 grid(SS / 128, SS / 128, BB * HH);
        qk_tc<<<grid, 256, QK_SMEM>>>(qkv, mask, w_out);
    }
    // 3) softmax rows in place
    softmax_rows<<<BB * HH * SS, 256>>>(w_out);
    // 4) a_heads = W @ V -> merged g_am (rounded)
    {
        dim3 grid(SS / 128, BB * HH);
        av_tc<<<grid, 256, V_SMEM>>>(w_out, qkv, am);
    }
    // 5) a = am @ w_proj + b_proj -> a_out (exact)
    {
        dim3 grid(DD / 128, BB * SS / 128);
        gemm_tc<false><<<grid, 256, G_SMEM>>>(am, wptf, b_proj, a_out,
                                              DD, DD, DD, DD);
    }
}